// round 1
// baseline (speedup 1.0000x reference)
#include <cuda_runtime.h>
#include <math.h>

#define NN 100000
#define NE 1600000
#define ET (NE + NN)
#define DH 64
#define NG 64

// ---- scratch (device globals; no allocation allowed) ----
__device__ __align__(16) float g_h[NN * DH];    // projected features h = x @ W
__device__ __align__(16) float g_acc[NN * DH];  // aggregation accumulator
__device__ __align__(16) float g_x[NN * DH];    // activated layer output / next input
__device__ float g_s[NN];                       // h . a_src per node
__device__ float g_d[NN];                       // h . a_dst per node
__device__ float g_m[NN];                       // segment max per dst
__device__ float g_den[NN];                     // segment sum of exp per dst
__device__ float g_vn[NG * DH];                 // pooled virtual-node features

__device__ __forceinline__ void atomicMaxF(float* a, float v) {
    if (v >= 0.f) atomicMax((int*)a, __float_as_int(v));
    else          atomicMin((unsigned int*)a, __float_as_uint(v));
}

// ---------------------------------------------------------------------------
// dst[n,c] = sum_k in[n,k] * W[k,c] (+ bias).  If a_src != null, also computes
// per-node scores  g_s[n] = dst_row . a_src,  g_d[n] = dst_row . a_dst.
// Tile: 32 nodes x 64 cols per block of 256 threads, 8 outputs/thread.
// ---------------------------------------------------------------------------
__global__ void k_matmul(const float* __restrict__ xin, const float* __restrict__ W,
                         const float* __restrict__ bias, float* __restrict__ dst,
                         const float* __restrict__ a_src, const float* __restrict__ a_dst) {
    __shared__ float Ws[DH * DH];
    __shared__ float xs[32 * DH];
    int t = threadIdx.x;
#pragma unroll
    for (int i = 0; i < 16; i++) Ws[t + 256 * i] = W[t + 256 * i];
    int base = blockIdx.x * 32;
#pragma unroll
    for (int i = 0; i < 8; i++) {
        int idx = t + 256 * i;  // 0..2047
        xs[idx] = xin[(size_t)base * DH + idx];
    }
    __syncthreads();

    int tx = t & 31;   // col base (cols tx and tx+32)
    int ty = t >> 5;   // warp id = node group (4 nodes each)

    float b0 = bias ? bias[tx] : 0.f;
    float b1 = bias ? bias[tx + 32] : 0.f;
    float acc[4][2];
#pragma unroll
    for (int j = 0; j < 4; j++) { acc[j][0] = b0; acc[j][1] = b1; }

#pragma unroll
    for (int k = 0; k < DH; k++) {
        float w0 = Ws[k * DH + tx];
        float w1 = Ws[k * DH + tx + 32];
#pragma unroll
        for (int j = 0; j < 4; j++) {
            float xv = xs[(ty * 4 + j) * DH + k];  // warp-uniform broadcast
            acc[j][0] = fmaf(xv, w0, acc[j][0]);
            acc[j][1] = fmaf(xv, w1, acc[j][1]);
        }
    }

    float as0 = 0.f, as1 = 0.f, ad0 = 0.f, ad1 = 0.f;
    if (a_src) { as0 = a_src[tx]; as1 = a_src[tx + 32]; ad0 = a_dst[tx]; ad1 = a_dst[tx + 32]; }

#pragma unroll
    for (int j = 0; j < 4; j++) {
        int n = base + ty * 4 + j;
        dst[(size_t)n * DH + tx]      = acc[j][0];
        dst[(size_t)n * DH + tx + 32] = acc[j][1];
        if (a_src) {
            float ss = acc[j][0] * as0 + acc[j][1] * as1;
            float dd = acc[j][0] * ad0 + acc[j][1] * ad1;
#pragma unroll
            for (int o = 16; o; o >>= 1) {
                ss += __shfl_xor_sync(0xffffffffu, ss, o);
                dd += __shfl_xor_sync(0xffffffffu, dd, o);
            }
            if (tx == 0) { g_s[n] = ss; g_d[n] = dd; }
        }
    }
}

// ---- zero accumulator + reset per-node softmax state ----
__global__ void k_init() {
    int i = blockIdx.x * blockDim.x + threadIdx.x;
    if (i < NN * DH) g_acc[i] = 0.f;
    if (i < NN) { g_m[i] = -INFINITY; g_den[i] = 0.f; }
}

__device__ __forceinline__ void edge_sd(const int* __restrict__ ei, int i, int& s, int& d) {
    if (i < NE) { s = ei[i]; d = ei[NE + i]; }
    else        { s = d = i - NE; }  // self loop
}

__global__ void k_emax(const int* __restrict__ ei) {
    int i = blockIdx.x * blockDim.x + threadIdx.x;
    if (i >= ET) return;
    int s, d; edge_sd(ei, i, s, d);
    float e = g_s[s] + g_d[d];
    e = e > 0.f ? e : 0.2f * e;
    atomicMaxF(&g_m[d], e);
}

__global__ void k_eden(const int* __restrict__ ei) {
    int i = blockIdx.x * blockDim.x + threadIdx.x;
    if (i >= ET) return;
    int s, d; edge_sd(ei, i, s, d);
    float e = g_s[s] + g_d[d];
    e = e > 0.f ? e : 0.2f * e;
    atomicAdd(&g_den[d], __expf(e - g_m[d]));
}

// 16 threads per edge; each does a v4 reduction of 4 cols.
__global__ void k_eacc(const int* __restrict__ ei) {
    int gt = blockIdx.x * blockDim.x + threadIdx.x;
    int i = gt >> 4;
    int l = gt & 15;
    if (i >= ET) return;
    int s, d; edge_sd(ei, i, s, d);
    float e = g_s[s] + g_d[d];
    e = e > 0.f ? e : 0.2f * e;
    float alpha = __expf(e - g_m[d]) / (g_den[d] + 1e-16f);
    float4 h4 = *(const float4*)(g_h + (size_t)s * DH + l * 4);
    float4 v;
    v.x = h4.x * alpha; v.y = h4.y * alpha; v.z = h4.z * alpha; v.w = h4.w * alpha;
    float* p = g_acc + (size_t)d * DH + l * 4;
    asm volatile("red.global.add.v4.f32 [%0], {%1,%2,%3,%4};"
                 :: "l"(p), "f"(v.x), "f"(v.y), "f"(v.z), "f"(v.w) : "memory");
}

// ---- g_x = leaky_relu(g_acc + b, 0.01) ----
__global__ void k_act(const float* __restrict__ b) {
    int i = blockIdx.x * blockDim.x + threadIdx.x;
    if (i >= NN * DH) return;
    float v = g_acc[i] + b[i & 63];
    g_x[i] = v > 0.f ? v : 0.01f * v;
}

// ---- virtual node: init with embedding, pool (batch is sorted) ----
__global__ void k_vninit(const float* __restrict__ emb) {
    int i = blockIdx.x * blockDim.x + threadIdx.x;
    if (i < NG * DH) g_vn[i] = emb[i & 63];
}

__global__ void k_pool(const int* __restrict__ batch) {
    int c = threadIdx.x;  // 0..63
    int n0 = blockIdx.x * 256;
    int n1 = n0 + 256; if (n1 > NN) n1 = NN;
    if (n0 >= NN) return;
    float acc = 0.f;
    int cur = batch[n0];
    for (int n = n0; n < n1; n++) {
        int bb = batch[n];
        if (bb != cur) { atomicAdd(&g_vn[cur * DH + c], acc); acc = 0.f; cur = bb; }
        acc += g_x[(size_t)n * DH + c];
    }
    atomicAdd(&g_vn[cur * DH + c], acc);
}

// ---- 4-layer MLP on vn, one block (64 threads) per graph ----
__global__ void k_vnmlp(const float* __restrict__ W1, const float* __restrict__ b1,
                        const float* __restrict__ W2, const float* __restrict__ b2,
                        const float* __restrict__ W3, const float* __restrict__ b3,
                        const float* __restrict__ W4, const float* __restrict__ b4,
                        float* __restrict__ outp) {
    __shared__ float r[64];
    int g = blockIdx.x, c = threadIdx.x;
    r[c] = g_vn[g * DH + c];
    __syncthreads();
    const float* Ws[4] = {W1, W2, W3, W4};
    const float* bs[4] = {b1, b2, b3, b4};
    for (int L = 0; L < 4; L++) {
        float acc = bs[L][c];
        for (int k = 0; k < 64; k++) acc = fmaf(r[k], Ws[L][k * 64 + c], acc);
        __syncthreads();
        r[c] = acc > 0.f ? acc : 0.f;
        __syncthreads();
    }
    outp[g * DH + c] = r[c];
}

extern "C" void kernel_launch(void* const* d_in, const int* in_sizes, int n_in,
                              void* d_out, int out_size) {
    const float* x     = (const float*)d_in[0];
    const int*   ei    = (const int*)d_in[1];
    const int*   batch = (const int*)d_in[2];
    // num_graphs may be passed as a size-1 input at index 3; detect and skip it.
    int o = (in_sizes[3] <= 16) ? 4 : 3;
    const float* W[3], *asr[3], *adt[3], *bb[3];
    for (int i = 0; i < 3; i++) {
        W[i]   = (const float*)d_in[o + 4 * i + 0];
        asr[i] = (const float*)d_in[o + 4 * i + 1];
        adt[i] = (const float*)d_in[o + 4 * i + 2];
        bb[i]  = (const float*)d_in[o + 4 * i + 3];
    }
    const float* Wout = (const float*)d_in[o + 12];
    const float* bout = (const float*)d_in[o + 13];
    const float* vne  = (const float*)d_in[o + 14];
    const float* Wm1 = (const float*)d_in[o + 15], *bm1 = (const float*)d_in[o + 16];
    const float* Wm2 = (const float*)d_in[o + 17], *bm2 = (const float*)d_in[o + 18];
    const float* Wf1 = (const float*)d_in[o + 19], *bf1 = (const float*)d_in[o + 20];
    const float* Wf2 = (const float*)d_in[o + 21], *bf2 = (const float*)d_in[o + 22];

    float *ph = nullptr, *px = nullptr;
    cudaGetSymbolAddress((void**)&ph, g_h);
    cudaGetSymbolAddress((void**)&px, g_x);

    float* out = (float*)d_out;

    const float* cur = x;
    for (int L = 0; L < 3; L++) {
        k_matmul<<<NN / 32, 256>>>(cur, W[L], nullptr, ph, asr[L], adt[L]);
        k_init<<<(NN * DH + 255) / 256, 256>>>();
        k_emax<<<(ET + 255) / 256, 256>>>(ei);
        k_eden<<<(ET + 255) / 256, 256>>>(ei);
        k_eacc<<<(ET * 16 + 255) / 256, 256>>>(ei);
        k_act<<<(NN * DH + 255) / 256, 256>>>(bb[L]);
        cur = px;
    }

    // final node projection: out[:NN*64] = g_x @ Wout + bout
    k_matmul<<<NN / 32, 256>>>(px, Wout, bout, out, nullptr, nullptr);

    // virtual node branch: pool + MLP -> out[NN*64 : NN*64 + NG*64]
    k_vninit<<<(NG * DH + 255) / 256, 256>>>(vne);
    k_pool<<<(NN + 255) / 256, 64>>>(batch);
    k_vnmlp<<<NG, 64>>>(Wm1, bm1, Wm2, bm2, Wf1, bf1, Wf2, bf2, out + (size_t)NN * DH);
}

// round 2
// speedup vs baseline: 1.6509x; 1.6509x over previous
#include <cuda_runtime.h>
#include <math.h>

#define NN 100000
#define NE 1600000
#define ET (NE + NN)
#define DH 64
#define NG 64
#define NB_SCAN 98   // ceil(NN/1024)

// ---- scratch (device globals) ----
__device__ __align__(16) float g_h[NN * DH];    // projected features h = x @ W
__device__ __align__(16) float g_x[NN * DH];    // activated layer output / next input
__device__ float g_s[NN];                       // h . a_src per node
__device__ float g_d[NN];                       // h . a_dst per node
__device__ float g_vn[NG * DH];                 // pooled virtual-node features
__device__ int   g_cnt[NN];                     // in-degree (incl. self loop)
__device__ int   g_row[NN + 1];                 // CSR row offsets (by dst)
__device__ int   g_woff[NN];                    // working offsets for scatter
__device__ int   g_csrc[ET];                    // CSR: src node per edge slot
__device__ int   g_bsum[128];                   // scan block sums
__device__ int   g_boff[128];                   // scanned block offsets

// ===========================================================================
// CSR build (edge_index is constant across layers -> build once per launch)
// ===========================================================================
__global__ void k_initcnt() {
    int i = blockIdx.x * blockDim.x + threadIdx.x;
    if (i < NN) g_cnt[i] = 1;  // self loop
}

__global__ void k_hist(const int* __restrict__ ei) {
    int i = blockIdx.x * blockDim.x + threadIdx.x;
    if (i < NE) atomicAdd(&g_cnt[ei[NE + i]], 1);
}

__global__ void k_scan1() {
    __shared__ int sm[1024];
    int t = threadIdx.x;
    int idx = blockIdx.x * 1024 + t;
    int v = (idx < NN) ? g_cnt[idx] : 0;
    sm[t] = v;
    __syncthreads();
#pragma unroll
    for (int o = 1; o < 1024; o <<= 1) {
        int nv = (t >= o) ? sm[t - o] : 0;
        __syncthreads();
        sm[t] += nv;
        __syncthreads();
    }
    if (idx < NN) g_row[idx] = sm[t] - v;  // exclusive
    if (t == 1023) g_bsum[blockIdx.x] = sm[1023];
}

__global__ void k_scan2() {
    __shared__ int sm[128];
    int t = threadIdx.x;
    int v = (t < NB_SCAN) ? g_bsum[t] : 0;
    sm[t] = v;
    __syncthreads();
#pragma unroll
    for (int o = 1; o < 128; o <<= 1) {
        int nv = (t >= o) ? sm[t - o] : 0;
        __syncthreads();
        sm[t] += nv;
        __syncthreads();
    }
    g_boff[t] = sm[t] - v;  // exclusive
}

__global__ void k_scan3() {
    int idx = blockIdx.x * blockDim.x + threadIdx.x;
    if (idx < NN) {
        int r = g_row[idx] + g_boff[idx >> 10];
        g_row[idx] = r;
        g_woff[idx] = r;
    }
    if (idx == 0) g_row[NN] = ET;
}

__global__ void k_scatter(const int* __restrict__ ei) {
    int i = blockIdx.x * blockDim.x + threadIdx.x;
    if (i >= ET) return;
    int s, d;
    if (i < NE) { s = ei[i]; d = ei[NE + i]; }
    else        { s = d = i - NE; }
    int pos = atomicAdd(&g_woff[d], 1);
    g_csrc[pos] = s;
}

// ===========================================================================
// matmul: dst[n,c] = sum_k in[n,k] * W[k,c] (+ bias); optionally attention dots
// 32 nodes x 64 cols per 256-thread block, 8 outputs/thread.
// ===========================================================================
__global__ void k_matmul(const float* __restrict__ xin, const float* __restrict__ W,
                         const float* __restrict__ bias, float* __restrict__ dst,
                         const float* __restrict__ a_src, const float* __restrict__ a_dst) {
    __shared__ float Ws[DH * DH];
    __shared__ float xs[32 * DH];
    int t = threadIdx.x;
#pragma unroll
    for (int i = 0; i < 16; i++) Ws[t + 256 * i] = W[t + 256 * i];
    int base = blockIdx.x * 32;
#pragma unroll
    for (int i = 0; i < 8; i++) {
        int idx = t + 256 * i;
        xs[idx] = xin[(size_t)base * DH + idx];
    }
    __syncthreads();

    int tx = t & 31;
    int ty = t >> 5;

    float b0 = bias ? bias[tx] : 0.f;
    float b1 = bias ? bias[tx + 32] : 0.f;
    float acc[4][2];
#pragma unroll
    for (int j = 0; j < 4; j++) { acc[j][0] = b0; acc[j][1] = b1; }

#pragma unroll
    for (int k = 0; k < DH; k += 4) {
        float4 x4[4];
#pragma unroll
        for (int j = 0; j < 4; j++)
            x4[j] = *(const float4*)&xs[(ty * 4 + j) * DH + k];
#pragma unroll
        for (int kk = 0; kk < 4; kk++) {
            float w0 = Ws[(k + kk) * DH + tx];
            float w1 = Ws[(k + kk) * DH + tx + 32];
#pragma unroll
            for (int j = 0; j < 4; j++) {
                float xv = kk == 0 ? x4[j].x : kk == 1 ? x4[j].y : kk == 2 ? x4[j].z : x4[j].w;
                acc[j][0] = fmaf(xv, w0, acc[j][0]);
                acc[j][1] = fmaf(xv, w1, acc[j][1]);
            }
        }
    }

    float as0 = 0.f, as1 = 0.f, ad0 = 0.f, ad1 = 0.f;
    if (a_src) { as0 = a_src[tx]; as1 = a_src[tx + 32]; ad0 = a_dst[tx]; ad1 = a_dst[tx + 32]; }

#pragma unroll
    for (int j = 0; j < 4; j++) {
        int n = base + ty * 4 + j;
        dst[(size_t)n * DH + tx]      = acc[j][0];
        dst[(size_t)n * DH + tx + 32] = acc[j][1];
        if (a_src) {
            float ss = acc[j][0] * as0 + acc[j][1] * as1;
            float dd = acc[j][0] * ad0 + acc[j][1] * ad1;
#pragma unroll
            for (int o = 16; o; o >>= 1) {
                ss += __shfl_xor_sync(0xffffffffu, ss, o);
                dd += __shfl_xor_sync(0xffffffffu, dd, o);
            }
            if (tx == 0) { g_s[n] = ss; g_d[n] = dd; }
        }
    }
}

// ===========================================================================
// Fused GAT softmax + aggregation + bias + leaky_relu(0.01).
// One warp per destination node. Pass 1: online softmax stats over in-edges
// (lane-strided). Pass 2: weighted gather of h[src] rows, 2 cols per lane.
// ===========================================================================
__global__ void k_agg(const float* __restrict__ bias, float* __restrict__ outp) {
    __shared__ float se[8][64];
    int w = threadIdx.x >> 5, lane = threadIdx.x & 31;
    int n = blockIdx.x * 8 + w;
    if (n >= NN) return;
    int rs = g_row[n], re = g_row[n + 1];
    float dval = g_d[n];

    float m = -1e30f, s = 0.f;
    for (int j = rs + lane; j < re; j += 32) {
        int src = g_csrc[j];
        float e = g_s[src] + dval;
        e = e > 0.f ? e : 0.2f * e;
        int o = j - rs;
        if (o < 64) se[w][o] = e;
        float nm = fmaxf(m, e);
        s = s * __expf(m - nm) + __expf(e - nm);
        m = nm;
    }
#pragma unroll
    for (int o = 16; o; o >>= 1) {
        float om = __shfl_xor_sync(0xffffffffu, m, o);
        float os = __shfl_xor_sync(0xffffffffu, s, o);
        float nm = fmaxf(m, om);
        s = s * __expf(m - nm) + os * __expf(om - nm);
        m = nm;
    }
    float inv = 1.f / (s + 1e-16f);
    __syncwarp();

    float acc0 = 0.f, acc1 = 0.f;
    int deg = re - rs;
    for (int o = 0; o < deg; o++) {
        int src = g_csrc[rs + o];  // broadcast
        float e;
        if (o < 64) e = se[w][o];
        else { e = g_s[src] + dval; e = e > 0.f ? e : 0.2f * e; }
        float a = __expf(e - m) * inv;
        acc0 = fmaf(a, g_h[(size_t)src * DH + lane], acc0);
        acc1 = fmaf(a, g_h[(size_t)src * DH + 32 + lane], acc1);
    }
    float v0 = acc0 + bias[lane];
    float v1 = acc1 + bias[lane + 32];
    outp[(size_t)n * DH + lane]      = v0 > 0.f ? v0 : 0.01f * v0;
    outp[(size_t)n * DH + 32 + lane] = v1 > 0.f ? v1 : 0.01f * v1;
}

// ---- virtual node: init with embedding, pool (batch is sorted) ----
__global__ void k_vninit(const float* __restrict__ emb) {
    int i = blockIdx.x * blockDim.x + threadIdx.x;
    if (i < NG * DH) g_vn[i] = emb[i & 63];
}

__global__ void k_pool(const int* __restrict__ batch) {
    int c = threadIdx.x;  // 0..63
    int n0 = blockIdx.x * 256;
    int n1 = n0 + 256; if (n1 > NN) n1 = NN;
    if (n0 >= NN) return;
    float acc = 0.f;
    int cur = batch[n0];
    for (int n = n0; n < n1; n++) {
        int bb = batch[n];
        if (bb != cur) { atomicAdd(&g_vn[cur * DH + c], acc); acc = 0.f; cur = bb; }
        acc += g_x[(size_t)n * DH + c];
    }
    atomicAdd(&g_vn[cur * DH + c], acc);
}

// ---- 4-layer MLP on vn, one block (64 threads) per graph ----
__global__ void k_vnmlp(const float* __restrict__ W1, const float* __restrict__ b1,
                        const float* __restrict__ W2, const float* __restrict__ b2,
                        const float* __restrict__ W3, const float* __restrict__ b3,
                        const float* __restrict__ W4, const float* __restrict__ b4,
                        float* __restrict__ outp) {
    __shared__ float r[64];
    int g = blockIdx.x, c = threadIdx.x;
    r[c] = g_vn[g * DH + c];
    __syncthreads();
    const float* Ws[4] = {W1, W2, W3, W4};
    const float* bs[4] = {b1, b2, b3, b4};
    for (int L = 0; L < 4; L++) {
        float acc = bs[L][c];
        for (int k = 0; k < 64; k++) acc = fmaf(r[k], Ws[L][k * 64 + c], acc);
        __syncthreads();
        r[c] = acc > 0.f ? acc : 0.f;
        __syncthreads();
    }
    outp[g * DH + c] = r[c];
}

extern "C" void kernel_launch(void* const* d_in, const int* in_sizes, int n_in,
                              void* d_out, int out_size) {
    const float* x     = (const float*)d_in[0];
    const int*   ei    = (const int*)d_in[1];
    const int*   batch = (const int*)d_in[2];
    int o = (in_sizes[3] <= 16) ? 4 : 3;
    const float* W[3], *asr[3], *adt[3], *bb[3];
    for (int i = 0; i < 3; i++) {
        W[i]   = (const float*)d_in[o + 4 * i + 0];
        asr[i] = (const float*)d_in[o + 4 * i + 1];
        adt[i] = (const float*)d_in[o + 4 * i + 2];
        bb[i]  = (const float*)d_in[o + 4 * i + 3];
    }
    const float* Wout = (const float*)d_in[o + 12];
    const float* bout = (const float*)d_in[o + 13];
    const float* vne  = (const float*)d_in[o + 14];
    const float* Wm1 = (const float*)d_in[o + 15], *bm1 = (const float*)d_in[o + 16];
    const float* Wm2 = (const float*)d_in[o + 17], *bm2 = (const float*)d_in[o + 18];
    const float* Wf1 = (const float*)d_in[o + 19], *bf1 = (const float*)d_in[o + 20];
    const float* Wf2 = (const float*)d_in[o + 21], *bf2 = (const float*)d_in[o + 22];

    float *ph = nullptr, *px = nullptr;
    cudaGetSymbolAddress((void**)&ph, g_h);
    cudaGetSymbolAddress((void**)&px, g_x);
    float* out = (float*)d_out;

    // ---- CSR build (once; reused by all 3 layers) ----
    k_initcnt<<<(NN + 255) / 256, 256>>>();
    k_hist<<<(NE + 255) / 256, 256>>>(ei);
    k_scan1<<<NB_SCAN, 1024>>>();
    k_scan2<<<1, 128>>>();
    k_scan3<<<(NN + 255) / 256, 256>>>();
    k_scatter<<<(ET + 255) / 256, 256>>>(ei);

    // ---- 3 GAT layers ----
    const float* cur = x;
    for (int L = 0; L < 3; L++) {
        k_matmul<<<NN / 32, 256>>>(cur, W[L], nullptr, ph, asr[L], adt[L]);
        k_agg<<<NN / 8, 256>>>(bb[L], px);
        cur = px;
    }

    // final node projection
    k_matmul<<<NN / 32, 256>>>(px, Wout, bout, out, nullptr, nullptr);

    // virtual node branch
    k_vninit<<<(NG * DH + 255) / 256, 256>>>(vne);
    k_pool<<<(NN + 255) / 256, 64>>>(batch);
    k_vnmlp<<<NG, 64>>>(Wm1, bm1, Wm2, bm2, Wf1, bf1, Wf2, bf2, out + (size_t)NN * DH);
}

// round 3
// speedup vs baseline: 1.6587x; 1.0048x over previous
#include <cuda_runtime.h>
#include <cuda_fp16.h>
#include <math.h>

#define NN 100000
#define NE 1600000
#define ET (NE + NN)
#define DH 64
#define NG 64
#define NB_SCAN 98   // ceil(NN/1024)

// ---- scratch (device globals) ----
__device__ __align__(16) __half2 g_h2[NN * 32];   // projected features (fp16, 2 cols/elt)
__device__ __align__(16) float g_x[NN * DH];      // activated layer output / next input
__device__ float g_s[NN];                         // h . a_src per node
__device__ float g_d[NN];                         // h . a_dst per node
__device__ float g_vn[NG * DH];                   // pooled virtual-node features
__device__ int   g_cnt[NN];                       // in-degree (incl. self loop)
__device__ int   g_row[NN + 1];                   // CSR row offsets (by dst)
__device__ int   g_woff[NN];                      // working offsets for scatter
__device__ int   g_csrc[ET];                      // CSR: src node per edge slot
__device__ int   g_bsum[128];
__device__ int   g_boff[128];

// ===========================================================================
// CSR build (edge_index constant across layers -> build once per launch)
// ===========================================================================
__global__ void k_initcnt() {
    int i = blockIdx.x * blockDim.x + threadIdx.x;
    if (i < NN) g_cnt[i] = 1;  // self loop
}

__global__ void k_hist(const int* __restrict__ ei) {
    int i = blockIdx.x * blockDim.x + threadIdx.x;
    if (i < NE) atomicAdd(&g_cnt[ei[NE + i]], 1);
}

__global__ void k_scan1() {
    __shared__ int sm[1024];
    int t = threadIdx.x;
    int idx = blockIdx.x * 1024 + t;
    int v = (idx < NN) ? g_cnt[idx] : 0;
    sm[t] = v;
    __syncthreads();
#pragma unroll
    for (int o = 1; o < 1024; o <<= 1) {
        int nv = (t >= o) ? sm[t - o] : 0;
        __syncthreads();
        sm[t] += nv;
        __syncthreads();
    }
    if (idx < NN) g_row[idx] = sm[t] - v;  // exclusive
    if (t == 1023) g_bsum[blockIdx.x] = sm[1023];
}

__global__ void k_scan2() {
    __shared__ int sm[128];
    int t = threadIdx.x;
    int v = (t < NB_SCAN) ? g_bsum[t] : 0;
    sm[t] = v;
    __syncthreads();
#pragma unroll
    for (int o = 1; o < 128; o <<= 1) {
        int nv = (t >= o) ? sm[t - o] : 0;
        __syncthreads();
        sm[t] += nv;
        __syncthreads();
    }
    g_boff[t] = sm[t] - v;  // exclusive
}

__global__ void k_scan3() {
    int idx = blockIdx.x * blockDim.x + threadIdx.x;
    if (idx < NN) {
        int r = g_row[idx] + g_boff[idx >> 10];
        g_row[idx] = r;
        g_woff[idx] = r;
    }
    if (idx == 0) g_row[NN] = ET;
}

__global__ void k_scatter(const int* __restrict__ ei) {
    int i = blockIdx.x * blockDim.x + threadIdx.x;
    if (i >= ET) return;
    int s, d;
    if (i < NE) { s = ei[i]; d = ei[NE + i]; }
    else        { s = d = i - NE; }
    int pos = atomicAdd(&g_woff[d], 1);
    g_csrc[pos] = s;
}

// ===========================================================================
// matmul: 64 nodes x 64 cols per 256-thread block. Lane tx -> cols 2tx,2tx+1.
// Writes fp16 half2 (layer path) or fp32 (final projection), plus attention dots.
// ===========================================================================
__global__ void __launch_bounds__(256) k_matmul(
        const float* __restrict__ xin, const float* __restrict__ W,
        const float* __restrict__ bias, float* __restrict__ dstF,
        __half2* __restrict__ dstH,
        const float* __restrict__ a_src, const float* __restrict__ a_dst) {
    __shared__ float Ws[DH * DH];
    __shared__ float xs[64 * DH];
    int t = threadIdx.x;
#pragma unroll
    for (int i = 0; i < 16; i++) Ws[t + 256 * i] = W[t + 256 * i];
    int base = blockIdx.x * 64;
#pragma unroll
    for (int i = 0; i < 16; i++) {
        int idx = t + 256 * i;  // 0..4095
        int g = base * DH + idx;
        xs[idx] = (g < NN * DH) ? xin[g] : 0.f;
    }
    __syncthreads();

    int tx = t & 31;   // lane -> cols 2tx, 2tx+1
    int ty = t >> 5;   // warp -> 8 nodes

    float b0 = bias ? bias[2 * tx] : 0.f;
    float b1 = bias ? bias[2 * tx + 1] : 0.f;
    float acc[8][2];
#pragma unroll
    for (int j = 0; j < 8; j++) { acc[j][0] = b0; acc[j][1] = b1; }

#pragma unroll
    for (int k = 0; k < DH; k += 4) {
        float4 xv[8];
#pragma unroll
        for (int j = 0; j < 8; j++)
            xv[j] = *(const float4*)&xs[(ty * 8 + j) * DH + k];
#pragma unroll
        for (int kk = 0; kk < 4; kk++) {
            float2 w = *(const float2*)&Ws[(k + kk) * DH + 2 * tx];
#pragma unroll
            for (int j = 0; j < 8; j++) {
                float xvv = (&xv[j].x)[kk];
                acc[j][0] = fmaf(xvv, w.x, acc[j][0]);
                acc[j][1] = fmaf(xvv, w.y, acc[j][1]);
            }
        }
    }

    float as0 = 0.f, as1 = 0.f, ad0 = 0.f, ad1 = 0.f;
    if (a_src) { as0 = a_src[2 * tx]; as1 = a_src[2 * tx + 1];
                 ad0 = a_dst[2 * tx]; ad1 = a_dst[2 * tx + 1]; }

#pragma unroll
    for (int j = 0; j < 8; j++) {
        int n = base + ty * 8 + j;
        if (n >= NN) break;
        if (dstH) g_h2[(size_t)n * 32 + tx] = __floats2half2_rn(acc[j][0], acc[j][1]);
        if (dstF) *(float2*)&dstF[(size_t)n * DH + 2 * tx] = make_float2(acc[j][0], acc[j][1]);
        if (a_src) {
            float ss = acc[j][0] * as0 + acc[j][1] * as1;
            float dd = acc[j][0] * ad0 + acc[j][1] * ad1;
#pragma unroll
            for (int o = 16; o; o >>= 1) {
                ss += __shfl_xor_sync(0xffffffffu, ss, o);
                dd += __shfl_xor_sync(0xffffffffu, dd, o);
            }
            if (tx == 0) { g_s[n] = ss; g_d[n] = dd; }
        }
    }
}

// ===========================================================================
// Fused single-pass GAT: online softmax + weighted gather + bias + leaky_relu.
// One warp per destination node; lane covers cols 2*lane, 2*lane+1 (one half2).
// ===========================================================================
__global__ void k_agg(const float* __restrict__ bias, float* __restrict__ outp) {
    int w = threadIdx.x >> 5, lane = threadIdx.x & 31;
    int n = blockIdx.x * 8 + w;
    if (n >= NN) return;
    int rs = g_row[n], re = g_row[n + 1];
    float dval = g_d[n];

    float m = -1e30f, s = 0.f, a0 = 0.f, a1 = 0.f;
#pragma unroll 4
    for (int j = rs; j < re; j++) {
        int src = __ldg(&g_csrc[j]);
        float e = __ldg(&g_s[src]) + dval;
        e = e > 0.f ? e : 0.2f * e;
        float2 f = __half22float2(g_h2[(size_t)src * 32 + lane]);
        float nm = fmaxf(m, e);
        float sc = __expf(m - nm);
        float p  = __expf(e - nm);
        s  = fmaf(s, sc, p);
        a0 = fmaf(a0, sc, p * f.x);
        a1 = fmaf(a1, sc, p * f.y);
        m = nm;
    }
    float inv = 1.f / (s + 1e-16f);
    float v0 = a0 * inv + bias[2 * lane];
    float v1 = a1 * inv + bias[2 * lane + 1];
    v0 = v0 > 0.f ? v0 : 0.01f * v0;
    v1 = v1 > 0.f ? v1 : 0.01f * v1;
    *(float2*)&outp[(size_t)n * DH + 2 * lane] = make_float2(v0, v1);
}

// ---- virtual node: init with embedding, pool (batch is sorted) ----
__global__ void k_vninit(const float* __restrict__ emb) {
    int i = blockIdx.x * blockDim.x + threadIdx.x;
    if (i < NG * DH) g_vn[i] = emb[i & 63];
}

__global__ void k_pool(const int* __restrict__ batch) {
    int c = threadIdx.x;  // 0..63
    int n0 = blockIdx.x * 256;
    int n1 = n0 + 256; if (n1 > NN) n1 = NN;
    if (n0 >= NN) return;
    float acc = 0.f;
    int cur = batch[n0];
    for (int n = n0; n < n1; n++) {
        int bb = batch[n];
        if (bb != cur) { atomicAdd(&g_vn[cur * DH + c], acc); acc = 0.f; cur = bb; }
        acc += g_x[(size_t)n * DH + c];
    }
    atomicAdd(&g_vn[cur * DH + c], acc);
}

// ---- 4-layer MLP on vn, one block (64 threads) per graph ----
__global__ void k_vnmlp(const float* __restrict__ W1, const float* __restrict__ b1,
                        const float* __restrict__ W2, const float* __restrict__ b2,
                        const float* __restrict__ W3, const float* __restrict__ b3,
                        const float* __restrict__ W4, const float* __restrict__ b4,
                        float* __restrict__ outp) {
    __shared__ float r[64];
    int g = blockIdx.x, c = threadIdx.x;
    r[c] = g_vn[g * DH + c];
    __syncthreads();
    const float* Ws[4] = {W1, W2, W3, W4};
    const float* bs[4] = {b1, b2, b3, b4};
    for (int L = 0; L < 4; L++) {
        float acc = bs[L][c];
        for (int k = 0; k < 64; k++) acc = fmaf(r[k], Ws[L][k * 64 + c], acc);
        __syncthreads();
        r[c] = acc > 0.f ? acc : 0.f;
        __syncthreads();
    }
    outp[g * DH + c] = r[c];
}

extern "C" void kernel_launch(void* const* d_in, const int* in_sizes, int n_in,
                              void* d_out, int out_size) {
    const float* x     = (const float*)d_in[0];
    const int*   ei    = (const int*)d_in[1];
    const int*   batch = (const int*)d_in[2];
    int o = (in_sizes[3] <= 16) ? 4 : 3;
    const float* W[3], *asr[3], *adt[3], *bb[3];
    for (int i = 0; i < 3; i++) {
        W[i]   = (const float*)d_in[o + 4 * i + 0];
        asr[i] = (const float*)d_in[o + 4 * i + 1];
        adt[i] = (const float*)d_in[o + 4 * i + 2];
        bb[i]  = (const float*)d_in[o + 4 * i + 3];
    }
    const float* Wout = (const float*)d_in[o + 12];
    const float* bout = (const float*)d_in[o + 13];
    const float* vne  = (const float*)d_in[o + 14];
    const float* Wm1 = (const float*)d_in[o + 15], *bm1 = (const float*)d_in[o + 16];
    const float* Wm2 = (const float*)d_in[o + 17], *bm2 = (const float*)d_in[o + 18];
    const float* Wf1 = (const float*)d_in[o + 19], *bf1 = (const float*)d_in[o + 20];
    const float* Wf2 = (const float*)d_in[o + 21], *bf2 = (const float*)d_in[o + 22];

    float *px = nullptr;
    __half2* ph2 = nullptr;
    cudaGetSymbolAddress((void**)&px, g_x);
    cudaGetSymbolAddress((void**)&ph2, g_h2);
    float* out = (float*)d_out;

    // ---- CSR build (once; reused by all 3 layers) ----
    k_initcnt<<<(NN + 255) / 256, 256>>>();
    k_hist<<<(NE + 255) / 256, 256>>>(ei);
    k_scan1<<<NB_SCAN, 1024>>>();
    k_scan2<<<1, 128>>>();
    k_scan3<<<(NN + 255) / 256, 256>>>();
    k_scatter<<<(ET + 255) / 256, 256>>>(ei);

    // ---- 3 GAT layers ----
    const float* cur = x;
    for (int L = 0; L < 3; L++) {
        k_matmul<<<(NN + 63) / 64, 256>>>(cur, W[L], nullptr, nullptr, ph2, asr[L], adt[L]);
        k_agg<<<(NN + 7) / 8, 256>>>(bb[L], px);
        cur = px;
    }

    // final node projection (fp32 out)
    k_matmul<<<(NN + 63) / 64, 256>>>(px, Wout, bout, out, nullptr, nullptr, nullptr);

    // virtual node branch
    k_vninit<<<(NG * DH + 255) / 256, 256>>>(vne);
    k_pool<<<(NN + 255) / 256, 64>>>(batch);
    k_vnmlp<<<NG, 64>>>(Wm1, bm1, Wm2, bm2, Wf1, bf1, Wf2, bf2, out + (size_t)NN * DH);
}